// round 3
// baseline (speedup 1.0000x reference)
#include <cuda_runtime.h>

#define BB 2
#define NQ 512
#define NK 512
#define D_EQUI 32
#define D_QINV 128
#define D_MSG 64
#define D_FF 128
#define D_OUT 64

// Precomputed per-row terms (scratch: __device__ globals, no allocation)
__device__ float g_qc[BB * NQ * D_FF];   // (q_msg @ W1[0:64]) + b1
__device__ float g_kc[BB * NK * D_FF];   // (k_msg @ W1[64:128])
__device__ float g_qn[BB * NQ * D_EQUI]; // |q_equi|^2 over spatial axis
__device__ float g_kn[BB * NK * D_EQUI];

// ---------------------------------------------------------------------------
// Prep kernels: one block per (b, row). 128 threads.
// ---------------------------------------------------------------------------
__global__ void prep_q_kernel(const float* __restrict__ q_equi,
                              const float* __restrict__ q_inv,
                              const float* __restrict__ Wq,
                              const float* __restrict__ bq,
                              const float* __restrict__ W1,
                              const float* __restrict__ b1) {
    int row = blockIdx.x;           // 0 .. B*NQ-1
    int t = threadIdx.x;            // 0 .. 127
    __shared__ float msg[D_MSG];
    if (t < D_MSG) {
        float acc = bq[t];
        const float* qi = q_inv + (size_t)row * D_QINV;
        #pragma unroll 8
        for (int i = 0; i < D_QINV; i++) acc = fmaf(qi[i], Wq[i * D_MSG + t], acc);
        msg[t] = acc;
    }
    __syncthreads();
    {
        float acc = b1[t];
        #pragma unroll 8
        for (int m = 0; m < D_MSG; m++) acc = fmaf(msg[m], W1[m * D_FF + t], acc);
        g_qc[(size_t)row * D_FF + t] = acc;
    }
    if (t < D_EQUI) {
        const float* qe = q_equi + (size_t)row * 3 * D_EQUI;
        float s = qe[t] * qe[t];
        s = fmaf(qe[D_EQUI + t], qe[D_EQUI + t], s);
        s = fmaf(qe[2 * D_EQUI + t], qe[2 * D_EQUI + t], s);
        g_qn[(size_t)row * D_EQUI + t] = s;
    }
}

__global__ void prep_k_kernel(const float* __restrict__ k_equi,
                              const float* __restrict__ k_inv,
                              const float* __restrict__ Wk,
                              const float* __restrict__ bk,
                              const float* __restrict__ W1) {
    int row = blockIdx.x;
    int t = threadIdx.x;
    __shared__ float msg[D_MSG];
    if (t < D_MSG) {
        float acc = bk[t];
        const float* ki = k_inv + (size_t)row * D_QINV;
        #pragma unroll 8
        for (int i = 0; i < D_QINV; i++) acc = fmaf(ki[i], Wk[i * D_MSG + t], acc);
        msg[t] = acc;
    }
    __syncthreads();
    {
        float acc = 0.0f;
        #pragma unroll 8
        for (int m = 0; m < D_MSG; m++)
            acc = fmaf(msg[m], W1[(D_MSG + m) * D_FF + t], acc);
        g_kc[(size_t)row * D_FF + t] = acc;
    }
    if (t < D_EQUI) {
        const float* ke = k_equi + (size_t)row * 3 * D_EQUI;
        float s = ke[t] * ke[t];
        s = fmaf(ke[D_EQUI + t], ke[D_EQUI + t], s);
        s = fmaf(ke[2 * D_EQUI + t], ke[2 * D_EQUI + t], s);
        g_kn[(size_t)row * D_EQUI + t] = s;
    }
}

// ---------------------------------------------------------------------------
// Main pairwise kernel: 16x16 pair tile per block, 1 pair per thread.
// ---------------------------------------------------------------------------
// All float4-accessed regions are aligned up to a multiple of 4 floats (16B).
#define ALIGN4(x) (((x) + 3) & ~3)
#define SM_W1P 0
#define SM_W2S (SM_W1P + 64 * 128)
#define SM_QES (SM_W2S + 128 * 64)
#define SM_KES (SM_QES + 16 * 101)
#define SM_QCS ALIGN4(SM_KES + 16 * 101)
#define SM_KCS (SM_QCS + 16 * 132)
#define SM_QNS (SM_KCS + 16 * 132)
#define SM_KNS (SM_QNS + 16 * 32)
#define SM_B2S ALIGN4(SM_KNS + 16 * 32)
#define SM_TOTAL_FLOATS (SM_B2S + 64)
#define SMEM_BYTES (SM_TOTAL_FLOATS * 4)

__global__ __launch_bounds__(256, 1)
void pair_kernel(const float* __restrict__ q_equi,
                 const float* __restrict__ k_equi,
                 const float* __restrict__ W1,
                 const float* __restrict__ W2,
                 const float* __restrict__ b2,
                 float* __restrict__ out) {
    extern __shared__ float smem[];
    float* W1p = smem + SM_W1P;
    float* W2s = smem + SM_W2S;
    float* qes = smem + SM_QES;
    float* kes = smem + SM_KES;
    float* qcs = smem + SM_QCS;
    float* kcs = smem + SM_KCS;
    float* qns = smem + SM_QNS;
    float* kns = smem + SM_KNS;
    float* b2s = smem + SM_B2S;

    const int tid = threadIdx.x;
    const int b  = blockIdx.z;
    const int q0 = blockIdx.y * 16;
    const int k0 = blockIdx.x * 16;

    // ---- cooperative loads ----
    // W1 pairwise rows 128..191 (dot: e=0..31, dist: e=32..63)
    for (int i = tid; i < 64 * 128; i += 256) W1p[i] = W1[128 * D_FF + i];
    for (int i = tid; i < 128 * 64; i += 256) W2s[i] = W2[i];
    for (int i = tid; i < 16 * 96; i += 256) {
        int r = i / 96, j = i % 96;
        qes[r * 101 + j] = q_equi[((size_t)(b * NQ + q0 + r)) * 96 + j];
        kes[r * 101 + j] = k_equi[((size_t)(b * NK + k0 + r)) * 96 + j];
    }
    for (int i = tid; i < 16 * 128; i += 256) {
        int r = i / 128, j = i % 128;
        qcs[r * 132 + j] = g_qc[(size_t)(b * NQ + q0 + r) * 128 + j];
        kcs[r * 132 + j] = g_kc[(size_t)(b * NK + k0 + r) * 128 + j];
    }
    for (int i = tid; i < 512; i += 256) {
        qns[i] = g_qn[(size_t)(b * NQ + q0) * 32 + i];
        kns[i] = g_kn[(size_t)(b * NK + k0) * 32 + i];
    }
    if (tid < 64) b2s[tid] = b2[tid];
    __syncthreads();

    const int tk = tid & 15;
    const int tq = tid >> 4;

    // ---- per-pair features: dot[32] and dist[32] ----
    const float* qrow = qes + tq * 101;
    const float* krow = kes + tk * 101;
    const float* qn = qns + tq * 32;
    const float* kn = kns + tk * 32;

    float v[64];
    #pragma unroll
    for (int e = 0; e < 32; e++) {
        float d = qrow[e] * krow[e];
        d = fmaf(qrow[32 + e], krow[32 + e], d);
        d = fmaf(qrow[64 + e], krow[64 + e], d);
        v[e] = d;
        float s = qn[e] + kn[e] - 2.0f * d;
        v[32 + e] = sqrtf(fmaxf(s, 0.0f));
    }

    // ---- out accumulators, init with b2 ----
    float acc[64];
    #pragma unroll
    for (int o4 = 0; o4 < 16; o4++) {
        float4 t = ((const float4*)b2s)[o4];
        acc[4 * o4 + 0] = t.x; acc[4 * o4 + 1] = t.y;
        acc[4 * o4 + 2] = t.z; acc[4 * o4 + 3] = t.w;
    }

    const float4* qc4 = (const float4*)(qcs + tq * 132);
    const float4* kc4 = (const float4*)(kcs + tk * 132);
    const float4* W1p4 = (const float4*)W1p;
    const float4* W2s4 = (const float4*)W2s;

    // ---- main loop over D_FF in groups of 4 (kept rolled: 32 iterations) ----
    for (int f4 = 0; f4 < 32; f4++) {
        float4 a = qc4[f4];
        float4 c = kc4[f4];
        float h0 = a.x + c.x, h1 = a.y + c.y, h2 = a.z + c.z, h3 = a.w + c.w;
        #pragma unroll
        for (int e = 0; e < 64; e++) {
            float4 w = W1p4[e * 32 + f4];
            h0 = fmaf(v[e], w.x, h0);
            h1 = fmaf(v[e], w.y, h1);
            h2 = fmaf(v[e], w.z, h2);
            h3 = fmaf(v[e], w.w, h3);
        }
        // silu
        h0 = __fdividef(h0, 1.0f + __expf(-h0));
        h1 = __fdividef(h1, 1.0f + __expf(-h1));
        h2 = __fdividef(h2, 1.0f + __expf(-h2));
        h3 = __fdividef(h3, 1.0f + __expf(-h3));
        // accumulate into out: rows 4*f4..4*f4+3 of W2
        #pragma unroll
        for (int o4 = 0; o4 < 16; o4++) {
            float4 w0 = W2s4[(4 * f4 + 0) * 16 + o4];
            float4 w1 = W2s4[(4 * f4 + 1) * 16 + o4];
            float4 w2 = W2s4[(4 * f4 + 2) * 16 + o4];
            float4 w3 = W2s4[(4 * f4 + 3) * 16 + o4];
            float r0 = acc[4 * o4 + 0], r1 = acc[4 * o4 + 1];
            float r2 = acc[4 * o4 + 2], r3 = acc[4 * o4 + 3];
            r0 = fmaf(h0, w0.x, r0); r0 = fmaf(h1, w1.x, r0);
            r0 = fmaf(h2, w2.x, r0); r0 = fmaf(h3, w3.x, r0);
            r1 = fmaf(h0, w0.y, r1); r1 = fmaf(h1, w1.y, r1);
            r1 = fmaf(h2, w2.y, r1); r1 = fmaf(h3, w3.y, r1);
            r2 = fmaf(h0, w0.z, r2); r2 = fmaf(h1, w1.z, r2);
            r2 = fmaf(h2, w2.z, r2); r2 = fmaf(h3, w3.z, r2);
            r3 = fmaf(h0, w0.w, r3); r3 = fmaf(h1, w1.w, r3);
            r3 = fmaf(h2, w2.w, r3); r3 = fmaf(h3, w3.w, r3);
            acc[4 * o4 + 0] = r0; acc[4 * o4 + 1] = r1;
            acc[4 * o4 + 2] = r2; acc[4 * o4 + 3] = r3;
        }
    }

    // ---- store [b, q, k, 64] ----
    float* op = out + (((size_t)(b * NQ + q0 + tq) * NK) + (k0 + tk)) * D_OUT;
    #pragma unroll
    for (int o4 = 0; o4 < 16; o4++) {
        ((float4*)op)[o4] = make_float4(acc[4 * o4 + 0], acc[4 * o4 + 1],
                                        acc[4 * o4 + 2], acc[4 * o4 + 3]);
    }
}

// ---------------------------------------------------------------------------
extern "C" void kernel_launch(void* const* d_in, const int* in_sizes, int n_in,
                              void* d_out, int out_size) {
    const float* q_equi = (const float*)d_in[0];
    const float* q_inv  = (const float*)d_in[1];
    const float* k_equi = (const float*)d_in[2];
    const float* k_inv  = (const float*)d_in[3];
    const float* Wq     = (const float*)d_in[4];
    const float* bq     = (const float*)d_in[5];
    const float* Wk     = (const float*)d_in[6];
    const float* bk     = (const float*)d_in[7];
    const float* W1     = (const float*)d_in[8];
    const float* b1     = (const float*)d_in[9];
    const float* W2     = (const float*)d_in[10];
    const float* b2     = (const float*)d_in[11];
    float* out = (float*)d_out;

    static int smem_set = 0;
    if (!smem_set) {
        cudaFuncSetAttribute(pair_kernel,
                             cudaFuncAttributeMaxDynamicSharedMemorySize,
                             SMEM_BYTES);
        smem_set = 1;
    }

    prep_q_kernel<<<BB * NQ, 128>>>(q_equi, q_inv, Wq, bq, W1, b1);
    prep_k_kernel<<<BB * NK, 128>>>(k_equi, k_inv, Wk, bk, W1);
    pair_kernel<<<dim3(NK / 16, NQ / 16, BB), 256, SMEM_BYTES>>>(
        q_equi, k_equi, W1, W2, b2, out);
}

// round 4
// speedup vs baseline: 1.3146x; 1.3146x over previous
#include <cuda_runtime.h>
#include <cstdint>

#define BB 2
#define NQ 512
#define NK 512
#define D_FF 128

// Precomputed per-row GEMM-1 halves (b1 folded into qc)
__device__ float g_qc[BB * NQ * D_FF];
__device__ float g_kc[BB * NK * D_FF];

// ---------------------------------------------------------------------------
// Prep kernels: one block per (b,row), 128 threads, 2-way ILP on the chains.
// ---------------------------------------------------------------------------
__global__ void prep_q_kernel(const float* __restrict__ q_inv,
                              const float* __restrict__ Wq,
                              const float* __restrict__ bq,
                              const float* __restrict__ W1,
                              const float* __restrict__ b1) {
    int row = blockIdx.x;
    int t = threadIdx.x;
    __shared__ float msg[64];
    if (t < 64) {
        const float* qi = q_inv + (size_t)row * 128;
        float a0 = bq[t], a1 = 0.f;
        #pragma unroll 4
        for (int i = 0; i < 128; i += 2) {
            a0 = fmaf(qi[i],     Wq[i * 64 + t],       a0);
            a1 = fmaf(qi[i + 1], Wq[(i + 1) * 64 + t], a1);
        }
        msg[t] = a0 + a1;
    }
    __syncthreads();
    {
        float a0 = b1[t], a1 = 0.f;
        #pragma unroll 4
        for (int m = 0; m < 64; m += 2) {
            a0 = fmaf(msg[m],     W1[m * 128 + t],       a0);
            a1 = fmaf(msg[m + 1], W1[(m + 1) * 128 + t], a1);
        }
        g_qc[(size_t)row * 128 + t] = a0 + a1;
    }
}

__global__ void prep_k_kernel(const float* __restrict__ k_inv,
                              const float* __restrict__ Wk,
                              const float* __restrict__ bk,
                              const float* __restrict__ W1) {
    int row = blockIdx.x;
    int t = threadIdx.x;
    __shared__ float msg[64];
    if (t < 64) {
        const float* ki = k_inv + (size_t)row * 128;
        float a0 = bk[t], a1 = 0.f;
        #pragma unroll 4
        for (int i = 0; i < 128; i += 2) {
            a0 = fmaf(ki[i],     Wk[i * 64 + t],       a0);
            a1 = fmaf(ki[i + 1], Wk[(i + 1) * 64 + t], a1);
        }
        msg[t] = a0 + a1;
    }
    __syncthreads();
    {
        float a0 = 0.f, a1 = 0.f;
        #pragma unroll 4
        for (int m = 0; m < 64; m += 2) {
            a0 = fmaf(msg[m],     W1[(64 + m) * 128 + t],     a0);
            a1 = fmaf(msg[m + 1], W1[(64 + m + 1) * 128 + t], a1);
        }
        g_kc[(size_t)row * 128 + t] = a0 + a1;
    }
}

// ---------------------------------------------------------------------------
// tf32 mma helpers
// ---------------------------------------------------------------------------
// Column permutation within each 8-group so that A-fragment k-columns
// (tig, tig+4) sit adjacent in shared memory -> LDS.64 fragment loads.
__device__ __forceinline__ int permc(int c) {
    int r = c & 7;
    return (c & ~7) | ((r < 4) ? (2 * r) : (2 * (r - 4) + 1));
}
__device__ __forceinline__ float tf32r(float x) {
    uint32_t u;
    asm("cvt.rna.tf32.f32 %0, %1;" : "=r"(u) : "f"(x));
    return __uint_as_float(u);
}
__device__ __forceinline__ void mma8(float* d, float a0, float a1, float a2, float a3,
                                     float b0, float b1) {
    asm("mma.sync.aligned.m16n8k8.row.col.f32.tf32.tf32.f32 "
        "{%0,%1,%2,%3}, {%4,%5,%6,%7}, {%8,%9}, {%0,%1,%2,%3};"
        : "+f"(d[0]), "+f"(d[1]), "+f"(d[2]), "+f"(d[3])
        : "r"(__float_as_uint(a0)), "r"(__float_as_uint(a1)),
          "r"(__float_as_uint(a2)), "r"(__float_as_uint(a3)),
          "r"(__float_as_uint(b0)), "r"(__float_as_uint(b1)));
}

// ---------------------------------------------------------------------------
// Pair kernel: 128 pairs (8q x 16k) per 256-thread block.
// GEMM-1: A[128x88] @ B1[88x128]  (K-extension folds qc/kc adds via one-hots)
// GEMM-2: silu(H)[128x128] @ W2[128x64] + b2
// ---------------------------------------------------------------------------
#define SW1_S 132     /* stride mod 16 == 4 -> conflict-free B-frag LDS.32 */
#define SW2_S 68
#define SA_S  104     /* stride mod 32 == 8 -> conflict-free A-frag LDS.64 */
#define SH_S  136

#define SW1_OFF 0
#define SW2_OFF (SW1_OFF + 88 * SW1_S)     /* 11616 */
#define SA_OFF  (SW2_OFF + 128 * SW2_S)    /* 20320 */
#define SH_OFF  (SA_OFF + 128 * SA_S)      /* 33632 */
#define B2_OFF  (SH_OFF + 128 * SH_S)      /* 51040 */
#define SM_FLOATS (B2_OFF + 64)            /* 51104 */
#define SMEM_BYTES (SM_FLOATS * 4)         /* 204416 < 227KB */

__global__ __launch_bounds__(256, 1)
void pair_mma_kernel(const float* __restrict__ q_equi,
                     const float* __restrict__ k_equi,
                     const float* __restrict__ W1,
                     const float* __restrict__ W2,
                     const float* __restrict__ b2,
                     float* __restrict__ out) {
    extern __shared__ float sm[];
    float* sW1 = sm + SW1_OFF;
    float* sW2 = sm + SW2_OFF;
    float* sA  = sm + SA_OFF;
    float* sH  = sm + SH_OFF;
    float* b2s = sm + B2_OFF;
    float* qes = sH;              // alias: live only until phase-2/3 sync
    float* kes = sH + 8 * 96;

    const int tid = threadIdx.x;
    const int b   = blockIdx.z;
    const int q0  = blockIdx.y * 8;
    const int k0  = blockIdx.x * 16;

    // ---- phase 1: stage weights (tf32-rounded, row-permuted) + equi tiles ----
    for (int i = tid; i < 64 * 128; i += 256) {
        int rl = i >> 7, n = i & 127;
        sW1[permc(rl) * SW1_S + n] = tf32r(W1[(128 + rl) * D_FF + n]);
    }
    for (int i = tid; i < 8 * 128; i += 256) {
        int j = i >> 7, n = i & 127;
        sW1[permc(64 + j) * SW1_S + n] =
            tf32r(g_qc[(size_t)(b * NQ + q0 + j) * D_FF + n]);
    }
    for (int i = tid; i < 16 * 128; i += 256) {
        int j = i >> 7, n = i & 127;
        sW1[permc(72 + j) * SW1_S + n] =
            tf32r(g_kc[(size_t)(b * NK + k0 + j) * D_FF + n]);
    }
    for (int i = tid; i < 128 * 64; i += 256) {
        int k = i >> 6, n = i & 63;
        sW2[permc(k) * SW2_S + n] = tf32r(W2[k * 64 + n]);
    }
    if (tid < 64) b2s[tid] = b2[tid];
    for (int i = tid; i < 8 * 96; i += 256)
        qes[i] = q_equi[(size_t)(b * NQ + q0) * 96 + i];
    for (int i = tid; i < 16 * 96; i += 256)
        kes[i] = k_equi[(size_t)(b * NK + k0) * 96 + i];
    __syncthreads();

    // ---- phase 2: per-pair features -> sA (2 threads per pair) ----
    {
        int p = tid >> 1, h = tid & 1;
        int ql = p >> 4, kl = p & 15;
        const float* qr = qes + ql * 96;
        const float* kr = kes + kl * 96;
        float* ar = sA + p * SA_S;
        #pragma unroll
        for (int e = 16 * h; e < 16 * h + 16; e++) {
            float qa = qr[e], qb = qr[32 + e], qc2 = qr[64 + e];
            float ka = kr[e], kb = kr[32 + e], kc2 = kr[64 + e];
            float dot = qa * ka + qb * kb + qc2 * kc2;
            float d0 = qa - ka, d1 = qb - kb, d2 = qc2 - kc2;
            float dist = sqrtf(d0 * d0 + d1 * d1 + d2 * d2);
            ar[permc(e)]      = tf32r(dot);
            ar[permc(32 + e)] = tf32r(dist);
        }
        #pragma unroll
        for (int c = 64 + 12 * h; c < 76 + 12 * h; c++) ar[permc(c)] = 0.0f;
        if (h == 0) ar[permc(64 + ql)] = 1.0f;   // one-hot q  (exact in tf32)
        else        ar[permc(72 + kl)] = 1.0f;   // one-hot k
    }
    __syncthreads();

    const int warp = tid >> 5, lane = tid & 31;
    const int wm = warp >> 1, wn = warp & 1;   // 4 m-strips x 2 n-strips
    const int g = lane >> 2, t = lane & 3;

    // ---- phase 3: GEMM-1 (M=128, this warp: rows wm*32..+32, cols wn*64..+64, K=88)
    float acc1[2][8][4];
    #pragma unroll
    for (int mt = 0; mt < 2; mt++)
        #pragma unroll
        for (int nt = 0; nt < 8; nt++)
            #pragma unroll
            for (int r = 0; r < 4; r++) acc1[mt][nt][r] = 0.f;

    for (int kk = 0; kk < 11; kk++) {
        int ks = kk * 8 + 2 * t;   // stored (permuted) k-column base
        float b0[8], b1[8];
        #pragma unroll
        for (int nt = 0; nt < 8; nt++) {
            int n = wn * 64 + nt * 8 + g;
            b0[nt] = sW1[ks * SW1_S + n];
            b1[nt] = sW1[(ks + 1) * SW1_S + n];
        }
        #pragma unroll
        for (int mt = 0; mt < 2; mt++) {
            int m = wm * 32 + mt * 16 + g;
            float2 lo = *(const float2*)(sA + m * SA_S + ks);
            float2 hi = *(const float2*)(sA + (m + 8) * SA_S + ks);
            #pragma unroll
            for (int nt = 0; nt < 8; nt++)
                mma8(acc1[mt][nt], lo.x, hi.x, lo.y, hi.y, b0[nt], b1[nt]);
        }
    }
    // epilogue: silu -> sH (tf32-rounded, permuted cols)
    #pragma unroll
    for (int mt = 0; mt < 2; mt++) {
        int m = wm * 32 + mt * 16 + g;
        #pragma unroll
        for (int nt = 0; nt < 8; nt++) {
            int nb = wn * 64 + nt * 8 + 2 * t;
            float* a = acc1[mt][nt];
            float h0 = __fdividef(a[0], 1.f + __expf(-a[0]));
            float h1 = __fdividef(a[1], 1.f + __expf(-a[1]));
            float h2 = __fdividef(a[2], 1.f + __expf(-a[2]));
            float h3 = __fdividef(a[3], 1.f + __expf(-a[3]));
            sH[m * SH_S + permc(nb)]           = tf32r(h0);
            sH[m * SH_S + permc(nb + 1)]       = tf32r(h1);
            sH[(m + 8) * SH_S + permc(nb)]     = tf32r(h2);
            sH[(m + 8) * SH_S + permc(nb + 1)] = tf32r(h3);
        }
    }
    __syncthreads();

    // ---- phase 4: GEMM-2 (rows wm*32..+32, cols wn*32..+32, K=128) ----
    float acc2[2][4][4];
    #pragma unroll
    for (int mt = 0; mt < 2; mt++)
        #pragma unroll
        for (int nt = 0; nt < 4; nt++)
            #pragma unroll
            for (int r = 0; r < 4; r++) acc2[mt][nt][r] = 0.f;

    for (int kk = 0; kk < 16; kk++) {
        int ks = kk * 8 + 2 * t;
        float b0[4], b1[4];
        #pragma unroll
        for (int nt = 0; nt < 4; nt++) {
            int n = wn * 32 + nt * 8 + g;
            b0[nt] = sW2[ks * SW2_S + n];
            b1[nt] = sW2[(ks + 1) * SW2_S + n];
        }
        #pragma unroll
        for (int mt = 0; mt < 2; mt++) {
            int m = wm * 32 + mt * 16 + g;
            float2 lo = *(const float2*)(sH + m * SH_S + ks);
            float2 hi = *(const float2*)(sH + (m + 8) * SH_S + ks);
            #pragma unroll
            for (int nt = 0; nt < 4; nt++)
                mma8(acc2[mt][nt], lo.x, hi.x, lo.y, hi.y, b0[nt], b1[nt]);
        }
    }
    // epilogue: + b2, direct store (pair p -> q=q0+p/16, k=k0+p%16)
    #pragma unroll
    for (int nt = 0; nt < 4; nt++) {
        int nb = wn * 32 + nt * 8 + 2 * t;
        float2 bb = *(const float2*)(b2s + nb);
        #pragma unroll
        for (int mt = 0; mt < 2; mt++) {
            int p  = wm * 32 + mt * 16 + g;
            int qq = q0 + (p >> 4);
            int kq = k0 + (p & 15);
            float* a = acc2[mt][nt];
            size_t base0 = ((size_t)(b * NQ + qq) * NK + kq) * 64 + nb;
            size_t base1 = ((size_t)(b * NQ + qq) * NK + (kq + 8)) * 64 + nb;
            *(float2*)(out + base0) = make_float2(a[0] + bb.x, a[1] + bb.y);
            *(float2*)(out + base1) = make_float2(a[2] + bb.x, a[3] + bb.y);
        }
    }
}

// ---------------------------------------------------------------------------
extern "C" void kernel_launch(void* const* d_in, const int* in_sizes, int n_in,
                              void* d_out, int out_size) {
    const float* q_equi = (const float*)d_in[0];
    const float* q_inv  = (const float*)d_in[1];
    const float* k_equi = (const float*)d_in[2];
    const float* k_inv  = (const float*)d_in[3];
    const float* Wq     = (const float*)d_in[4];
    const float* bq     = (const float*)d_in[5];
    const float* Wk     = (const float*)d_in[6];
    const float* bk     = (const float*)d_in[7];
    const float* W1     = (const float*)d_in[8];
    const float* b1     = (const float*)d_in[9];
    const float* W2     = (const float*)d_in[10];
    const float* b2     = (const float*)d_in[11];
    float* out = (float*)d_out;

    static int smem_set = 0;
    if (!smem_set) {
        cudaFuncSetAttribute(pair_mma_kernel,
                             cudaFuncAttributeMaxDynamicSharedMemorySize,
                             SMEM_BYTES);
        smem_set = 1;
    }

    prep_q_kernel<<<BB * NQ, 128>>>(q_inv, Wq, bq, W1, b1);
    prep_k_kernel<<<BB * NK, 128>>>(k_inv, Wk, bk, W1);
    pair_mma_kernel<<<dim3(NK / 16, NQ / 8, BB), 256, SMEM_BYTES>>>(
        q_equi, k_equi, W1, W2, b2, out);
}

// round 5
// speedup vs baseline: 2.0166x; 1.5340x over previous
#include <cuda_runtime.h>
#include <cstdint>

#define BB 2
#define NQ 512
#define NK 512
#define D_FF 128

#define QT_PER_B (NQ / 8)      /* 64 q-tiles */
#define KT_PER_B (NK / 16)     /* 32 k-tiles */
#define N_TILES (BB * QT_PER_B * KT_PER_B)   /* 4096 */
#define N_BLOCKS 148

// Precomputed per-row GEMM-1 halves (b1 folded into qc)
__device__ float g_qc[BB * NQ * D_FF];
__device__ float g_kc[BB * NK * D_FF];

// ---------------------------------------------------------------------------
// Fused prep kernel: blocks [0,1024) -> q rows, [1024,2048) -> k rows.
// ---------------------------------------------------------------------------
__global__ void prep_kernel(const float* __restrict__ q_inv,
                            const float* __restrict__ k_inv,
                            const float* __restrict__ Wq,
                            const float* __restrict__ bq,
                            const float* __restrict__ Wk,
                            const float* __restrict__ bk,
                            const float* __restrict__ W1,
                            const float* __restrict__ b1) {
    int bid = blockIdx.x;
    int t = threadIdx.x;
    __shared__ float msg[64];
    if (bid < BB * NQ) {
        int row = bid;
        if (t < 64) {
            const float* qi = q_inv + (size_t)row * 128;
            float a0 = bq[t], a1 = 0.f;
            #pragma unroll 4
            for (int i = 0; i < 128; i += 2) {
                a0 = fmaf(qi[i],     Wq[i * 64 + t],       a0);
                a1 = fmaf(qi[i + 1], Wq[(i + 1) * 64 + t], a1);
            }
            msg[t] = a0 + a1;
        }
        __syncthreads();
        float a0 = b1[t], a1 = 0.f;
        #pragma unroll 4
        for (int m = 0; m < 64; m += 2) {
            a0 = fmaf(msg[m],     W1[m * 128 + t],       a0);
            a1 = fmaf(msg[m + 1], W1[(m + 1) * 128 + t], a1);
        }
        g_qc[(size_t)row * 128 + t] = a0 + a1;
    } else {
        int row = bid - BB * NQ;
        if (t < 64) {
            const float* ki = k_inv + (size_t)row * 128;
            float a0 = bk[t], a1 = 0.f;
            #pragma unroll 4
            for (int i = 0; i < 128; i += 2) {
                a0 = fmaf(ki[i],     Wk[i * 64 + t],       a0);
                a1 = fmaf(ki[i + 1], Wk[(i + 1) * 64 + t], a1);
            }
            msg[t] = a0 + a1;
        }
        __syncthreads();
        float a0 = 0.f, a1 = 0.f;
        #pragma unroll 4
        for (int m = 0; m < 64; m += 2) {
            a0 = fmaf(msg[m],     W1[(64 + m) * 128 + t],     a0);
            a1 = fmaf(msg[m + 1], W1[(64 + m + 1) * 128 + t], a1);
        }
        g_kc[(size_t)row * 128 + t] = a0 + a1;
    }
}

// ---------------------------------------------------------------------------
// tf32 mma helpers
// ---------------------------------------------------------------------------
// Column permutation: logical k-col c -> stored pos so that the fragment pair
// (t, t+4) sits at stored (2t, 2t+1) -> one LDS.64 per fragment.
__device__ __forceinline__ int permc(int c) {
    int r = c & 7;
    return (c & ~7) | ((r < 4) ? (2 * r) : (2 * (r - 4) + 1));
}
__device__ __forceinline__ float tf32r(float x) {
    uint32_t u;
    asm("cvt.rna.tf32.f32 %0, %1;" : "=r"(u) : "f"(x));
    return __uint_as_float(u);
}
__device__ __forceinline__ void mma8(float* d, float a0, float a1, float a2, float a3,
                                     float b0, float b1) {
    asm("mma.sync.aligned.m16n8k8.row.col.f32.tf32.tf32.f32 "
        "{%0,%1,%2,%3}, {%4,%5,%6,%7}, {%8,%9}, {%0,%1,%2,%3};"
        : "+f"(d[0]), "+f"(d[1]), "+f"(d[2]), "+f"(d[3])
        : "r"(__float_as_uint(a0)), "r"(__float_as_uint(a1)),
          "r"(__float_as_uint(a2)), "r"(__float_as_uint(a3)),
          "r"(__float_as_uint(b0)), "r"(__float_as_uint(b1)));
}

// ---------------------------------------------------------------------------
// Persistent pair kernel. Per tile: 128 pairs (8q x 16k).
// GEMM-1: A[128x88] @ B1[88x128]  (one-hot K-extension folds qc/kc adds)
// GEMM-2: silu(H)[128x128] @ W2[128x64] + b2
// Layouts: B matrices k-contiguous (transposed), stride 136 (==8 mod 64)
//          -> all fragment LDS.64 conflict-free. A/H share one buffer.
// ---------------------------------------------------------------------------
#define BST 136
#define SW1T_OFF 0                          /* [n=128][k 136] */
#define SW2T_OFF (SW1T_OFF + 128 * BST)     /* [n=64][k 136]  */
#define SA_OFF   (SW2T_OFF + 64 * BST)      /* [m=128][k 136] A then H */
#define QES_OFF  (SA_OFF + 128 * BST)       /* 8 x 97  */
#define KES_OFF  (QES_OFF + 8 * 97)         /* 16 x 97 */
#define B2_OFF   (KES_OFF + 16 * 97)
#define SM_FLOATS (B2_OFF + 64)
#define SMEM_BYTES (SM_FLOATS * 4)          /* 183,648 B */

__global__ __launch_bounds__(256, 1)
void pair_mma_kernel(const float* __restrict__ q_equi,
                     const float* __restrict__ k_equi,
                     const float* __restrict__ W1,
                     const float* __restrict__ W2,
                     const float* __restrict__ b2,
                     float* __restrict__ out) {
    extern __shared__ float sm[];
    float* sW1T = sm + SW1T_OFF;
    float* sW2T = sm + SW2T_OFF;
    float* sA   = sm + SA_OFF;    // A for GEMM-1, reused as H for GEMM-2
    float* qes  = sm + QES_OFF;
    float* kes  = sm + KES_OFF;
    float* b2s  = sm + B2_OFF;

    const int tid = threadIdx.x;

    // ---- one-time weight staging (tf32-rounded, k-permuted, transposed) ----
    for (int i = tid; i < 64 * 128; i += 256) {
        int rl = i >> 7, n = i & 127;
        sW1T[n * BST + permc(rl)] = tf32r(W1[(128 + rl) * D_FF + n]);
    }
    for (int i = tid; i < 128 * 64; i += 256) {
        int k = i >> 6, n = i & 63;
        sW2T[n * BST + permc(k)] = tf32r(W2[k * 64 + n]);
    }
    if (tid < 64) b2s[tid] = b2[tid];

    const int warp = tid >> 5, lane = tid & 31;
    const int wm = warp >> 1, wn = warp & 1;   // 4 m-strips x 2 n-strips
    const int g = lane >> 2, t = lane & 3;

    const int fp = tid >> 1, fh = tid & 1;     // feature phase: 2 thr/pair
    const int fql = fp >> 4, fkl = fp & 15;

    for (int tile = blockIdx.x; tile < N_TILES; tile += N_BLOCKS) {
        const int b  = tile / (QT_PER_B * KT_PER_B);
        const int r  = tile % (QT_PER_B * KT_PER_B);
        const int q0 = (r / KT_PER_B) * 8;
        const int k0 = (r % KT_PER_B) * 16;

        __syncthreads();   // prior tile fully read sW1T qc/kc cols + sH

        // ---- stage qc/kc into one-hot columns of sW1T ----
        for (int i = tid; i < 8 * 128; i += 256) {
            int n = i >> 3, j = i & 7;
            sW1T[n * BST + permc(64 + j)] =
                tf32r(g_qc[(size_t)(b * NQ + q0 + j) * D_FF + n]);
        }
        for (int i = tid; i < 16 * 128; i += 256) {
            int n = i >> 4, j = i & 15;
            sW1T[n * BST + permc(72 + j)] =
                tf32r(g_kc[(size_t)(b * NK + k0 + j) * D_FF + n]);
        }
        // ---- stage equi tiles (stride 97 -> conflict-free reads) ----
        for (int i = tid; i < 8 * 96; i += 256)
            qes[(i / 96) * 97 + (i % 96)] = q_equi[(size_t)(b * NQ + q0) * 96 + i];
        for (int i = tid; i < 16 * 96; i += 256)
            kes[(i / 96) * 97 + (i % 96)] = k_equi[(size_t)(b * NK + k0) * 96 + i];
        __syncthreads();

        // ---- per-pair features -> sA ----
        {
            const float* qr = qes + fql * 97;
            const float* kr = kes + fkl * 97;
            float* ar = sA + fp * BST;
            #pragma unroll
            for (int e = 16 * fh; e < 16 * fh + 16; e++) {
                float qa = qr[e], qb = qr[32 + e], qc2 = qr[64 + e];
                float ka = kr[e], kb = kr[32 + e], kc2 = kr[64 + e];
                float dot = qa * ka + qb * kb + qc2 * kc2;
                float d0 = qa - ka, d1 = qb - kb, d2 = qc2 - kc2;
                float dist = sqrtf(d0 * d0 + d1 * d1 + d2 * d2);
                ar[permc(e)]      = tf32r(dot);
                ar[permc(32 + e)] = tf32r(dist);
            }
            #pragma unroll
            for (int c = 64 + 12 * fh; c < 76 + 12 * fh; c++) ar[permc(c)] = 0.0f;
            if (fh == 0) ar[permc(64 + fql)] = 1.0f;
            else         ar[permc(72 + fkl)] = 1.0f;
        }
        __syncthreads();

        // ---- GEMM-1: warp rows wm*32..+32, cols wn*64..+64, K=88 ----
        float acc1[2][8][4];
        #pragma unroll
        for (int mt = 0; mt < 2; mt++)
            #pragma unroll
            for (int nt = 0; nt < 8; nt++)
                #pragma unroll
                for (int rr = 0; rr < 4; rr++) acc1[mt][nt][rr] = 0.f;

        #pragma unroll
        for (int kk = 0; kk < 11; kk++) {
            int ks = kk * 8 + 2 * t;
            float2 bf[8];
            #pragma unroll
            for (int nt = 0; nt < 8; nt++) {
                int n = wn * 64 + nt * 8 + g;
                bf[nt] = *(const float2*)(sW1T + n * BST + ks);
            }
            #pragma unroll
            for (int mt = 0; mt < 2; mt++) {
                int m = wm * 32 + mt * 16 + g;
                float2 lo = *(const float2*)(sA + m * BST + ks);
                float2 hi = *(const float2*)(sA + (m + 8) * BST + ks);
                #pragma unroll
                for (int nt = 0; nt < 8; nt++)
                    mma8(acc1[mt][nt], lo.x, hi.x, lo.y, hi.y, bf[nt].x, bf[nt].y);
            }
        }
        __syncthreads();   // all sA reads done before H overwrites it

        // ---- epilogue 1: silu -> sH (aliases sA), permuted cols ----
        #pragma unroll
        for (int mt = 0; mt < 2; mt++) {
            int m = wm * 32 + mt * 16 + g;
            #pragma unroll
            for (int nt = 0; nt < 8; nt++) {
                int nb = wn * 64 + nt * 8 + 2 * t;
                float* a = acc1[mt][nt];
                float h0 = __fdividef(a[0], 1.f + __expf(-a[0]));
                float h1 = __fdividef(a[1], 1.f + __expf(-a[1]));
                float h2 = __fdividef(a[2], 1.f + __expf(-a[2]));
                float h3 = __fdividef(a[3], 1.f + __expf(-a[3]));
                sA[m * BST + permc(nb)]           = tf32r(h0);
                sA[m * BST + permc(nb + 1)]       = tf32r(h1);
                sA[(m + 8) * BST + permc(nb)]     = tf32r(h2);
                sA[(m + 8) * BST + permc(nb + 1)] = tf32r(h3);
            }
        }
        __syncthreads();

        // ---- GEMM-2: warp rows wm*32..+32, cols wn*32..+32, K=128 ----
        float acc2[2][4][4];
        #pragma unroll
        for (int mt = 0; mt < 2; mt++)
            #pragma unroll
            for (int nt = 0; nt < 4; nt++)
                #pragma unroll
                for (int rr = 0; rr < 4; rr++) acc2[mt][nt][rr] = 0.f;

        #pragma unroll
        for (int kk = 0; kk < 16; kk++) {
            int ks = kk * 8 + 2 * t;
            float2 bf[4];
            #pragma unroll
            for (int nt = 0; nt < 4; nt++) {
                int n = wn * 32 + nt * 8 + g;
                bf[nt] = *(const float2*)(sW2T + n * BST + ks);
            }
            #pragma unroll
            for (int mt = 0; mt < 2; mt++) {
                int m = wm * 32 + mt * 16 + g;
                float2 lo = *(const float2*)(sA + m * BST + ks);
                float2 hi = *(const float2*)(sA + (m + 8) * BST + ks);
                #pragma unroll
                for (int nt = 0; nt < 4; nt++)
                    mma8(acc2[mt][nt], lo.x, hi.x, lo.y, hi.y, bf[nt].x, bf[nt].y);
            }
        }

        // ---- epilogue 2: +b2, direct store ----
        #pragma unroll
        for (int nt = 0; nt < 4; nt++) {
            int nb = wn * 32 + nt * 8 + 2 * t;
            float2 bb = *(const float2*)(b2s + nb);
            #pragma unroll
            for (int mt = 0; mt < 2; mt++) {
                int p  = wm * 32 + mt * 16 + g;
                int qq = q0 + (p >> 4);
                int kq = k0 + (p & 15);
                float* a = acc2[mt][nt];
                size_t base0 = ((size_t)(b * NQ + qq) * NK + kq) * 64 + nb;
                size_t base1 = ((size_t)(b * NQ + qq) * NK + (kq + 8)) * 64 + nb;
                *(float2*)(out + base0) = make_float2(a[0] + bb.x, a[1] + bb.y);
                *(float2*)(out + base1) = make_float2(a[2] + bb.x, a[3] + bb.y);
            }
        }
    }
}

// ---------------------------------------------------------------------------
extern "C" void kernel_launch(void* const* d_in, const int* in_sizes, int n_in,
                              void* d_out, int out_size) {
    const float* q_equi = (const float*)d_in[0];
    const float* q_inv  = (const float*)d_in[1];
    const float* k_equi = (const float*)d_in[2];
    const float* k_inv  = (const float*)d_in[3];
    const float* Wq     = (const float*)d_in[4];
    const float* bq     = (const float*)d_in[5];
    const float* Wk     = (const float*)d_in[6];
    const float* bk     = (const float*)d_in[7];
    const float* W1     = (const float*)d_in[8];
    const float* b1     = (const float*)d_in[9];
    const float* W2     = (const float*)d_in[10];
    const float* b2     = (const float*)d_in[11];
    float* out = (float*)d_out;

    static int smem_set = 0;
    if (!smem_set) {
        cudaFuncSetAttribute(pair_mma_kernel,
                             cudaFuncAttributeMaxDynamicSharedMemorySize,
                             SMEM_BYTES);
        smem_set = 1;
    }

    prep_kernel<<<BB * (NQ + NK), 128>>>(q_inv, k_inv, Wq, bq, Wk, bk, W1, b1);
    pair_mma_kernel<<<N_BLOCKS, 256, SMEM_BYTES>>>(
        q_equi, k_equi, W1, W2, b2, out);
}

// round 9
// speedup vs baseline: 2.4652x; 1.2225x over previous
#include <cuda_runtime.h>
#include <cstdint>

#define BB 2
#define NQ 512
#define NK 512
#define D_FF 128

#define QT_PER_B (NQ / 8)
#define KT_PER_B (NK / 16)
#define N_TILES (BB * QT_PER_B * KT_PER_B)   /* 4096 */
#define N_BLOCKS 148
#define NTHR 512

// Per-row GEMM-1 halves (b1 folded into qc)
__device__ float g_qc[BB * NQ * D_FF];
__device__ float g_kc[BB * NK * D_FF];

// ---------------------------------------------------------------------------
// Prep kernel: blocks [0,1024) q rows, [1024,2048) k rows.
// ---------------------------------------------------------------------------
__global__ void prep_kernel(const float* __restrict__ q_inv,
                            const float* __restrict__ k_inv,
                            const float* __restrict__ Wq,
                            const float* __restrict__ bq,
                            const float* __restrict__ Wk,
                            const float* __restrict__ bk,
                            const float* __restrict__ W1,
                            const float* __restrict__ b1) {
    int bid = blockIdx.x;
    int t = threadIdx.x;
    __shared__ float msg[64];
    if (bid < BB * NQ) {
        int row = bid;
        if (t < 64) {
            const float* qi = q_inv + (size_t)row * 128;
            float a0 = bq[t], a1 = 0.f;
            #pragma unroll 4
            for (int i = 0; i < 128; i += 2) {
                a0 = fmaf(qi[i],     Wq[i * 64 + t],       a0);
                a1 = fmaf(qi[i + 1], Wq[(i + 1) * 64 + t], a1);
            }
            msg[t] = a0 + a1;
        }
        __syncthreads();
        float a0 = b1[t], a1 = 0.f;
        #pragma unroll 4
        for (int m = 0; m < 64; m += 2) {
            a0 = fmaf(msg[m],     W1[m * 128 + t],       a0);
            a1 = fmaf(msg[m + 1], W1[(m + 1) * 128 + t], a1);
        }
        g_qc[(size_t)row * 128 + t] = a0 + a1;
    } else {
        int row = bid - BB * NQ;
        if (t < 64) {
            const float* ki = k_inv + (size_t)row * 128;
            float a0 = bk[t], a1 = 0.f;
            #pragma unroll 4
            for (int i = 0; i < 128; i += 2) {
                a0 = fmaf(ki[i],     Wk[i * 64 + t],       a0);
                a1 = fmaf(ki[i + 1], Wk[(i + 1) * 64 + t], a1);
            }
            msg[t] = a0 + a1;
        }
        __syncthreads();
        float a0 = 0.f, a1 = 0.f;
        #pragma unroll 4
        for (int m = 0; m < 64; m += 2) {
            a0 = fmaf(msg[m],     W1[(64 + m) * 128 + t],     a0);
            a1 = fmaf(msg[m + 1], W1[(64 + m + 1) * 128 + t], a1);
        }
        g_kc[(size_t)row * 128 + t] = a0 + a1;
    }
}

// ---------------------------------------------------------------------------
// tf32 mma helpers (legacy mma.sync — the only tensor path on this target)
// ---------------------------------------------------------------------------
// Column permutation: fragment pair (t, t+4) stored adjacent as (2t, 2t+1).
__device__ __forceinline__ int permc(int c) {
    int r = c & 7;
    return (c & ~7) | ((r < 4) ? (2 * r) : (2 * (r - 4) + 1));
}
__device__ __forceinline__ float tf32r(float x) {
    uint32_t u;
    asm("cvt.rna.tf32.f32 %0, %1;" : "=r"(u) : "f"(x));
    return __uint_as_float(u);
}
__device__ __forceinline__ void mma8(float* d, float a0, float a1, float a2, float a3,
                                     float b0, float b1) {
    asm("mma.sync.aligned.m16n8k8.row.col.f32.tf32.tf32.f32 "
        "{%0,%1,%2,%3}, {%4,%5,%6,%7}, {%8,%9}, {%0,%1,%2,%3};"
        : "+f"(d[0]), "+f"(d[1]), "+f"(d[2]), "+f"(d[3])
        : "r"(__float_as_uint(a0)), "r"(__float_as_uint(a1)),
          "r"(__float_as_uint(a2)), "r"(__float_as_uint(a3)),
          "r"(__float_as_uint(b0)), "r"(__float_as_uint(b1)));
}

// ---------------------------------------------------------------------------
// SMEM layout (float offsets). Strides 72/136 (==8 mod 64) -> fragment LDS.64
// conflict-free per phase; 136 also conflict-free for epilogue kc reads.
// ---------------------------------------------------------------------------
#define SW1T_OFF 0                           /* [n=128][72]  W1 pairwise, k-contig */
#define SW2T_OFF (SW1T_OFF + 128 * 72)       /* [n=64][136]  W2, k-contig */
#define SA_OFF   (SW2T_OFF + 64 * 136)       /* [m=128][72]  features */
#define SH_OFF   (SA_OFF + 128 * 72)         /* [m=128][136] hidden */
#define QCS_OFF  (SH_OFF + 128 * 136)        /* 8  x 136 */
#define KCS_OFF  (QCS_OFF + 8 * 136)         /* 16 x 136 */
#define QES_OFF  (KCS_OFF + 16 * 136)        /* 8  x 97  */
#define KES_OFF  (QES_OFF + 8 * 97)          /* 16 x 97  */
#define B2S_OFF  (KES_OFF + 16 * 97)         /* 64 (even offset) */
#define SM_FLOATS (B2S_OFF + 64)
#define SMEM_BYTES (SM_FLOATS * 4)           /* 200,800 B */

__global__ __launch_bounds__(NTHR, 1)
void pair_mma_kernel(const float* __restrict__ q_equi,
                     const float* __restrict__ k_equi,
                     const float* __restrict__ W1,
                     const float* __restrict__ W2,
                     const float* __restrict__ b2,
                     float* __restrict__ out) {
    extern __shared__ float sm[];
    float* sW1T = sm + SW1T_OFF;
    float* sW2T = sm + SW2T_OFF;
    float* sA   = sm + SA_OFF;
    float* sH   = sm + SH_OFF;
    float* qcs  = sm + QCS_OFF;
    float* kcs  = sm + KCS_OFF;
    float* qes  = sm + QES_OFF;
    float* kes  = sm + KES_OFF;
    float* b2s  = sm + B2S_OFF;

    const int tid = threadIdx.x;

    // ---- one-time static staging (tf32-rounded, k-permuted, k-contiguous) ----
    for (int i = tid; i < 128 * 64; i += NTHR) {       // sW1T[n][c] = W1[128+c][n]
        int n = i >> 6, c = i & 63;
        sW1T[n * 72 + permc(c)] = tf32r(W1[(128 + c) * D_FF + n]);
    }
    for (int i = tid; i < 64 * 128; i += NTHR) {       // sW2T[n][k] = W2[k][n]
        int n = i >> 7, k = i & 127;
        sW2T[n * 136 + permc(k)] = tf32r(W2[k * 64 + n]);
    }
    if (tid < 64) b2s[tid] = b2[tid];

    const int warp = tid >> 5, lane = tid & 31;
    const int wm = warp >> 1, wn = warp & 1;   // 8 m-strips(16) x 2 n-strips
    const int g = lane >> 2, t = lane & 3;
    const int m0 = wm * 16;

    const int fp = tid >> 2, fh = tid & 3;     // feature phase: 4 thr/pair
    const int fql = fp >> 4, fkl = fp & 15;

    for (int tile = blockIdx.x; tile < N_TILES; tile += N_BLOCKS) {
        const int b  = tile / (QT_PER_B * KT_PER_B);
        const int r  = tile % (QT_PER_B * KT_PER_B);
        const int q0 = (r / KT_PER_B) * 8;
        const int k0 = (r % KT_PER_B) * 16;

        __syncthreads();   // prev tile fully consumed qcs/kcs/qes/kes/sA/sH

        // ---- per-tile staging ----
        for (int i = tid; i < 8 * 128; i += NTHR)
            qcs[(i >> 7) * 136 + (i & 127)] =
                g_qc[(size_t)(b * NQ + q0 + (i >> 7)) * D_FF + (i & 127)];
        for (int i = tid; i < 16 * 128; i += NTHR)
            kcs[(i >> 7) * 136 + (i & 127)] =
                g_kc[(size_t)(b * NK + k0 + (i >> 7)) * D_FF + (i & 127)];
        for (int i = tid; i < 8 * 96; i += NTHR)
            qes[(i / 96) * 97 + (i % 96)] = q_equi[(size_t)(b * NQ + q0) * 96 + i];
        for (int i = tid; i < 16 * 96; i += NTHR)
            kes[(i / 96) * 97 + (i % 96)] = k_equi[(size_t)(b * NK + k0) * 96 + i];
        __syncthreads();

        // ---- features -> sA (dot cols 0..31, dist cols 32..63) ----
        {
            const float* qr = qes + fql * 97;
            const float* kr = kes + fkl * 97;
            float* ar = sA + fp * 72;
            #pragma unroll
            for (int e = 8 * fh; e < 8 * fh + 8; e++) {
                float qa = qr[e], qb = qr[32 + e], qc2 = qr[64 + e];
                float ka = kr[e], kb = kr[32 + e], kc2 = kr[64 + e];
                float dot = qa * ka + qb * kb + qc2 * kc2;
                float d0 = qa - ka, d1 = qb - kb, d2 = qc2 - kc2;
                float dist = sqrtf(d0 * d0 + d1 * d1 + d2 * d2);
                ar[permc(e)]      = tf32r(dot);
                ar[permc(32 + e)] = tf32r(dist);
            }
        }
        __syncthreads();

        // ---- GEMM-1: rows m0..m0+15, cols wn*64..+64, K=64 ----
        float acc1[8][4];
        #pragma unroll
        for (int nt = 0; nt < 8; nt++)
            #pragma unroll
            for (int rr = 0; rr < 4; rr++) acc1[nt][rr] = 0.f;

        #pragma unroll
        for (int kk = 0; kk < 8; kk++) {
            int ks = kk * 8 + 2 * t;
            float2 bf[8];
            #pragma unroll
            for (int nt = 0; nt < 8; nt++)
                bf[nt] = *(const float2*)(sW1T + (wn * 64 + nt * 8 + g) * 72 + ks);
            float2 lo = *(const float2*)(sA + (m0 + g) * 72 + ks);
            float2 hi = *(const float2*)(sA + (m0 + 8 + g) * 72 + ks);
            #pragma unroll
            for (int nt = 0; nt < 8; nt++)
                mma8(acc1[nt], lo.x, hi.x, lo.y, hi.y, bf[nt].x, bf[nt].y);
        }

        // ---- epilogue 1: +qc +kc, silu, tf32 -> sH ----
        {
            const float* qrow  = qcs + wm * 136;        // warp-uniform (broadcast)
            const float* krow0 = kcs + g * 136;         // row g
            const float* krow1 = kcs + (g + 8) * 136;   // row g+8
            #pragma unroll
            for (int nt = 0; nt < 8; nt++) {
                int nb = wn * 64 + nt * 8 + 2 * t;
                float2 qv = *(const float2*)(qrow + nb);
                float2 k0v = *(const float2*)(krow0 + nb);
                float2 k1v = *(const float2*)(krow1 + nb);
                float h0 = acc1[nt][0] + qv.x + k0v.x;
                float h1 = acc1[nt][1] + qv.y + k0v.y;
                float h2 = acc1[nt][2] + qv.x + k1v.x;
                float h3 = acc1[nt][3] + qv.y + k1v.y;
                h0 = __fdividef(h0, 1.f + __expf(-h0));
                h1 = __fdividef(h1, 1.f + __expf(-h1));
                h2 = __fdividef(h2, 1.f + __expf(-h2));
                h3 = __fdividef(h3, 1.f + __expf(-h3));
                sH[(m0 + g) * 136 + permc(nb)]         = tf32r(h0);
                sH[(m0 + g) * 136 + permc(nb + 1)]     = tf32r(h1);
                sH[(m0 + 8 + g) * 136 + permc(nb)]     = tf32r(h2);
                sH[(m0 + 8 + g) * 136 + permc(nb + 1)] = tf32r(h3);
            }
        }
        __syncthreads();

        // ---- GEMM-2: rows m0..m0+15, cols wn*32..+32, K=128 ----
        float acc2[4][4];
        #pragma unroll
        for (int nt = 0; nt < 4; nt++)
            #pragma unroll
            for (int rr = 0; rr < 4; rr++) acc2[nt][rr] = 0.f;

        #pragma unroll
        for (int kk = 0; kk < 16; kk++) {
            int ks = kk * 8 + 2 * t;
            float2 bf[4];
            #pragma unroll
            for (int nt = 0; nt < 4; nt++)
                bf[nt] = *(const float2*)(sW2T + (wn * 32 + nt * 8 + g) * 136 + ks);
            float2 lo = *(const float2*)(sH + (m0 + g) * 136 + ks);
            float2 hi = *(const float2*)(sH + (m0 + 8 + g) * 136 + ks);
            #pragma unroll
            for (int nt = 0; nt < 4; nt++)
                mma8(acc2[nt], lo.x, hi.x, lo.y, hi.y, bf[nt].x, bf[nt].y);
        }

        // ---- epilogue 2: +b2, direct store ----
        #pragma unroll
        for (int nt = 0; nt < 4; nt++) {
            int nb = wn * 32 + nt * 8 + 2 * t;
            float2 bb = *(const float2*)(b2s + nb);
            int p0 = m0 + g, p1 = m0 + 8 + g;
            size_t o0 = ((size_t)(b * NQ + q0 + (p0 >> 4)) * NK + (k0 + (p0 & 15))) * 64 + nb;
            size_t o1 = ((size_t)(b * NQ + q0 + (p1 >> 4)) * NK + (k0 + (p1 & 15))) * 64 + nb;
            *(float2*)(out + o0) = make_float2(acc2[nt][0] + bb.x, acc2[nt][1] + bb.y);
            *(float2*)(out + o1) = make_float2(acc2[nt][2] + bb.x, acc2[nt][3] + bb.y);
        }
    }
}

// ---------------------------------------------------------------------------
extern "C" void kernel_launch(void* const* d_in, const int* in_sizes, int n_in,
                              void* d_out, int out_size) {
    const float* q_equi = (const float*)d_in[0];
    const float* q_inv  = (const float*)d_in[1];
    const float* k_equi = (const float*)d_in[2];
    const float* k_inv  = (const float*)d_in[3];
    const float* Wq     = (const float*)d_in[4];
    const float* bq     = (const float*)d_in[5];
    const float* Wk     = (const float*)d_in[6];
    const float* bk     = (const float*)d_in[7];
    const float* W1     = (const float*)d_in[8];
    const float* b1     = (const float*)d_in[9];
    const float* W2     = (const float*)d_in[10];
    const float* b2     = (const float*)d_in[11];
    float* out = (float*)d_out;

    static int smem_set = 0;
    if (!smem_set) {
        cudaFuncSetAttribute(pair_mma_kernel,
                             cudaFuncAttributeMaxDynamicSharedMemorySize,
                             SMEM_BYTES);
        smem_set = 1;
    }

    prep_kernel<<<BB * (NQ + NK), 128>>>(q_inv, k_inv, Wq, bq, Wk, bk, W1, b1);
    pair_mma_kernel<<<N_BLOCKS, NTHR, SMEM_BYTES>>>(
        q_equi, k_equi, W1, W2, b2, out);
}

// round 11
// speedup vs baseline: 3.4799x; 1.4116x over previous
#include <cuda_runtime.h>
#include <cuda_fp16.h>
#include <cstdint>

#define BB 2
#define NQ 512
#define NK 512
#define D_FF 128

#define QT2 (NQ / 16)
#define KT2 (NK / 16)
#define N_TILES2 (BB * QT2 * KT2)   /* 2048 double-tiles (16q x 16k = 256 pairs) */
#define N_BLOCKS 148
#define NTHR 512

// Per-row GEMM-1 halves (b1 folded into qc)
__device__ float g_qc[BB * NQ * D_FF];
__device__ float g_kc[BB * NK * D_FF];

// ---------------------------------------------------------------------------
// Prep kernel: blocks [0,1024) -> q rows, [1024,2048) -> k rows.
// ---------------------------------------------------------------------------
__global__ void prep_kernel(const float* __restrict__ q_inv,
                            const float* __restrict__ k_inv,
                            const float* __restrict__ Wq,
                            const float* __restrict__ bq,
                            const float* __restrict__ Wk,
                            const float* __restrict__ bk,
                            const float* __restrict__ W1,
                            const float* __restrict__ b1) {
    int bid = blockIdx.x;
    int t = threadIdx.x;
    __shared__ float msg[64];
    if (bid < BB * NQ) {
        int row = bid;
        if (t < 64) {
            const float* qi = q_inv + (size_t)row * 128;
            float a0 = bq[t], a1 = 0.f;
            #pragma unroll 4
            for (int i = 0; i < 128; i += 2) {
                a0 = fmaf(qi[i],     Wq[i * 64 + t],       a0);
                a1 = fmaf(qi[i + 1], Wq[(i + 1) * 64 + t], a1);
            }
            msg[t] = a0 + a1;
        }
        __syncthreads();
        float a0 = b1[t], a1 = 0.f;
        #pragma unroll 4
        for (int m = 0; m < 64; m += 2) {
            a0 = fmaf(msg[m],     W1[m * 128 + t],       a0);
            a1 = fmaf(msg[m + 1], W1[(m + 1) * 128 + t], a1);
        }
        g_qc[(size_t)row * 128 + t] = a0 + a1;
    } else {
        int row = bid - BB * NQ;
        if (t < 64) {
            const float* ki = k_inv + (size_t)row * 128;
            float a0 = bk[t], a1 = 0.f;
            #pragma unroll 4
            for (int i = 0; i < 128; i += 2) {
                a0 = fmaf(ki[i],     Wk[i * 64 + t],       a0);
                a1 = fmaf(ki[i + 1], Wk[(i + 1) * 64 + t], a1);
            }
            msg[t] = a0 + a1;
        }
        __syncthreads();
        float a0 = 0.f, a1 = 0.f;
        #pragma unroll 4
        for (int m = 0; m < 64; m += 2) {
            a0 = fmaf(msg[m],     W1[(64 + m) * 128 + t],     a0);
            a1 = fmaf(msg[m + 1], W1[(64 + m + 1) * 128 + t], a1);
        }
        g_kc[(size_t)row * 128 + t] = a0 + a1;
    }
}

// ---------------------------------------------------------------------------
// fp16 mma helpers
// ---------------------------------------------------------------------------
// Byte offset of logical column c (halves) within a row: columns grouped by 16,
// permuted so thread t's fragment {2t,2t+1,8+2t,8+2t+1} is contiguous (8 bytes).
__device__ __forceinline__ int colb(int c) {
    int r = c & 15;
    int pos = ((r & 6) << 1) + ((r >> 3) & 1) * 2 + (r & 1);
    return ((c >> 4) << 5) + pos * 2;
}
__device__ __forceinline__ uint32_t f2h2(float lo, float hi) {
    __half2 h = __floats2half2_rn(lo, hi);
    return *reinterpret_cast<uint32_t*>(&h);
}
__device__ __forceinline__ void mma16(float* d,
                                      uint32_t a0, uint32_t a1, uint32_t a2,
                                      uint32_t a3, uint32_t b0, uint32_t b1) {
    asm("mma.sync.aligned.m16n8k16.row.col.f32.f16.f16.f32 "
        "{%0,%1,%2,%3}, {%4,%5,%6,%7}, {%8,%9}, {%0,%1,%2,%3};"
        : "+f"(d[0]), "+f"(d[1]), "+f"(d[2]), "+f"(d[3])
        : "r"(a0), "r"(a1), "r"(a2), "r"(a3), "r"(b0), "r"(b1));
}

// ---------------------------------------------------------------------------
// SMEM layout (byte offsets). Row strides 160/288 bytes (==32 mod 128) make
// every fragment LDS.64 bank-conflict-free (8g+2t covers all 32 banks/phase).
// ---------------------------------------------------------------------------
#define SW1T 0                 /* 128 n-rows x 160 B (64 k halves)  */
#define SW2T 20480             /* 64  n-rows x 288 B (128 k halves) */
#define SA   38912             /* 256 m-rows x 160 B (64 halves)    */
#define SH   79872             /* 256 m-rows x 288 B (128 halves)   */
#define QCS  153600            /* 16 x 136 f32 */
#define KCS  162304            /* 16 x 136 f32 */
#define QES  171008            /* 16 x 97 f32  */
#define KES  177216            /* 16 x 97 f32  */
#define B2S  183424            /* 64 f32 */
#define SMEM_TOTAL 183680

__global__ __launch_bounds__(NTHR, 1)
void pair_mma_kernel(const float* __restrict__ q_equi,
                     const float* __restrict__ k_equi,
                     const float* __restrict__ W1,
                     const float* __restrict__ W2,
                     const float* __restrict__ b2,
                     float* __restrict__ out) {
    extern __shared__ char smc[];
    float* b2s = (float*)(smc + B2S);

    const int tid = threadIdx.x;

    // ---- one-time static staging: W1 pairwise rows + W2 as fp16, k-contig ----
    for (int i = tid; i < 128 * 64; i += NTHR) {     // sW1T[n][c] = W1[128+c][n]
        int n = i >> 6, c = i & 63;
        *(__half*)(smc + SW1T + n * 160 + colb(c)) =
            __float2half_rn(W1[(128 + c) * D_FF + n]);
    }
    for (int i = tid; i < 64 * 128; i += NTHR) {     // sW2T[n][k] = W2[k][n]
        int n = i >> 7, k = i & 127;
        *(__half*)(smc + SW2T + n * 288 + colb(k)) =
            __float2half_rn(W2[k * 64 + n]);
    }
    if (tid < 64) b2s[tid] = b2[tid];

    const int warp = tid >> 5, lane = tid & 31;
    const int wm = warp >> 1, wn = warp & 1;     // 8 m-strips(32) x 2 n-strips
    const int g = lane >> 2, t = lane & 3;
    const int m0 = wm * 32;

    const int fp = tid >> 1, fh = tid & 1;       // feature phase: 2 thr/pair
    const int fql = fp >> 4, fkl = fp & 15;

    for (int tile = blockIdx.x; tile < N_TILES2; tile += N_BLOCKS) {
        const int b  = tile / (QT2 * KT2);
        const int r  = tile % (QT2 * KT2);
        const int q0 = (r / KT2) * 16;
        const int k0 = (r % KT2) * 16;

        __syncthreads();   // prev iteration fully consumed dynamic buffers

        // ---- per-tile staging: qc/kc (f32) + equi tiles ----
        float* qcs = (float*)(smc + QCS);
        float* kcs = (float*)(smc + KCS);
        for (int i = tid; i < 16 * 128; i += NTHR)
            qcs[(i >> 7) * 136 + (i & 127)] =
                g_qc[(size_t)(b * NQ + q0 + (i >> 7)) * D_FF + (i & 127)];
        for (int i = tid; i < 16 * 128; i += NTHR)
            kcs[(i >> 7) * 136 + (i & 127)] =
                g_kc[(size_t)(b * NK + k0 + (i >> 7)) * D_FF + (i & 127)];
        float* qes = (float*)(smc + QES);
        float* kes = (float*)(smc + KES);
        for (int i = tid; i < 16 * 96; i += NTHR)
            qes[(i / 96) * 97 + (i % 96)] = q_equi[(size_t)(b * NQ + q0) * 96 + i];
        for (int i = tid; i < 16 * 96; i += NTHR)
            kes[(i / 96) * 97 + (i % 96)] = k_equi[(size_t)(b * NK + k0) * 96 + i];
        __syncthreads();

        // ---- features -> sA as fp16 (dot cols 0..31, dist cols 32..63) ----
        {
            const float* qr = qes + fql * 97;    // warp-uniform row
            const float* kr = kes + fkl * 97;
            char* ar = smc + SA + fp * 160;
            #pragma unroll
            for (int e = 16 * fh; e < 16 * fh + 16; e += 2) {
                float qa0 = qr[e], qb0 = qr[32 + e], qc0 = qr[64 + e];
                float ka0 = kr[e], kb0 = kr[32 + e], kc0 = kr[64 + e];
                float qa1 = qr[e + 1], qb1 = qr[33 + e], qc1 = qr[65 + e];
                float ka1 = kr[e + 1], kb1 = kr[33 + e], kc1 = kr[65 + e];
                float dot0 = qa0 * ka0 + qb0 * kb0 + qc0 * kc0;
                float dot1 = qa1 * ka1 + qb1 * kb1 + qc1 * kc1;
                float d0 = qa0 - ka0, d1 = qb0 - kb0, d2 = qc0 - kc0;
                float e0 = qa1 - ka1, e1 = qb1 - kb1, e2 = qc1 - kc1;
                float dist0 = sqrtf(d0 * d0 + d1 * d1 + d2 * d2);
                float dist1 = sqrtf(e0 * e0 + e1 * e1 + e2 * e2);
                *(uint32_t*)(ar + colb(e))      = f2h2(dot0, dot1);
                *(uint32_t*)(ar + colb(32 + e)) = f2h2(dist0, dist1);
            }
        }
        __syncthreads();

        // ---- GEMM-1: rows m0..m0+31, cols wn*64..+64, K=64 (4 k-slabs) ----
        float acc1[2][8][4];
        #pragma unroll
        for (int mt = 0; mt < 2; mt++)
            #pragma unroll
            for (int nt = 0; nt < 8; nt++)
                #pragma unroll
                for (int rr = 0; rr < 4; rr++) acc1[mt][nt][rr] = 0.f;

        #pragma unroll
        for (int kk = 0; kk < 4; kk++) {
            uint2 aLo[2], aHi[2];
            #pragma unroll
            for (int mt = 0; mt < 2; mt++) {
                const char* ap = smc + SA + (m0 + mt * 16 + g) * 160 + kk * 32 + t * 8;
                aLo[mt] = *(const uint2*)ap;
                aHi[mt] = *(const uint2*)(ap + 8 * 160);
            }
            #pragma unroll
            for (int nt = 0; nt < 8; nt++) {
                uint2 bf = *(const uint2*)(smc + SW1T +
                                           (wn * 64 + nt * 8 + g) * 160 + kk * 32 + t * 8);
                mma16(acc1[0][nt], aLo[0].x, aHi[0].x, aLo[0].y, aHi[0].y, bf.x, bf.y);
                mma16(acc1[1][nt], aLo[1].x, aHi[1].x, aLo[1].y, aHi[1].y, bf.x, bf.y);
            }
        }

        // ---- epilogue 1: +qc +kc, silu, fp16 -> sH ----
        #pragma unroll
        for (int mt = 0; mt < 2; mt++) {
            const float* qrow = qcs + (wm * 2 + mt) * 136;   // warp-uniform
            const float* kr0  = kcs + g * 136;
            const float* kr1  = kcs + (g + 8) * 136;
            char* h0p = smc + SH + (m0 + mt * 16 + g) * 288;
            char* h1p = h0p + 8 * 288;
            #pragma unroll
            for (int nt = 0; nt < 8; nt++) {
                int nb = wn * 64 + nt * 8 + 2 * t;
                float2 qv  = *(const float2*)(qrow + nb);
                float2 kv0 = *(const float2*)(kr0 + nb);
                float2 kv1 = *(const float2*)(kr1 + nb);
                float h0 = acc1[mt][nt][0] + qv.x + kv0.x;
                float h1 = acc1[mt][nt][1] + qv.y + kv0.y;
                float h2 = acc1[mt][nt][2] + qv.x + kv1.x;
                float h3 = acc1[mt][nt][3] + qv.y + kv1.y;
                h0 = __fdividef(h0, 1.f + __expf(-h0));
                h1 = __fdividef(h1, 1.f + __expf(-h1));
                h2 = __fdividef(h2, 1.f + __expf(-h2));
                h3 = __fdividef(h3, 1.f + __expf(-h3));
                int gb = ((wn * 4 + (nt >> 1)) << 5) + t * 8 + (nt & 1) * 4;
                *(uint32_t*)(h0p + gb) = f2h2(h0, h1);
                *(uint32_t*)(h1p + gb) = f2h2(h2, h3);
            }
        }
        __syncthreads();

        // ---- GEMM-2: rows m0..m0+31, cols wn*32..+32, K=128 (8 k-slabs) ----
        float acc2[2][4][4];
        #pragma unroll
        for (int mt = 0; mt < 2; mt++)
            #pragma unroll
            for (int nt = 0; nt < 4; nt++)
                #pragma unroll
                for (int rr = 0; rr < 4; rr++) acc2[mt][nt][rr] = 0.f;

        #pragma unroll
        for (int kk = 0; kk < 8; kk++) {
            uint2 aLo[2], aHi[2];
            #pragma unroll
            for (int mt = 0; mt < 2; mt++) {
                const char* ap = smc + SH + (m0 + mt * 16 + g) * 288 + kk * 32 + t * 8;
                aLo[mt] = *(const uint2*)ap;
                aHi[mt] = *(const uint2*)(ap + 8 * 288);
            }
            #pragma unroll
            for (int nt = 0; nt < 4; nt++) {
                uint2 bf = *(const uint2*)(smc + SW2T +
                                           (wn * 32 + nt * 8 + g) * 288 + kk * 32 + t * 8);
                mma16(acc2[0][nt], aLo[0].x, aHi[0].x, aLo[0].y, aHi[0].y, bf.x, bf.y);
                mma16(acc2[1][nt], aLo[1].x, aHi[1].x, aLo[1].y, aHi[1].y, bf.x, bf.y);
            }
        }

        // ---- epilogue 2: +b2, direct store (row p: jq=p>>4, jk=p&15) ----
        #pragma unroll
        for (int nt = 0; nt < 4; nt++) {
            int nb = wn * 32 + nt * 8 + 2 * t;
            float2 bb = *(const float2*)(b2s + nb);
            #pragma unroll
            for (int mt = 0; mt < 2; mt++) {
                int p0 = m0 + mt * 16 + g;
                int p1 = p0 + 8;
                size_t o0 = ((size_t)(b * NQ + q0 + (p0 >> 4)) * NK + (k0 + (p0 & 15))) * 64 + nb;
                size_t o1 = ((size_t)(b * NQ + q0 + (p1 >> 4)) * NK + (k0 + (p1 & 15))) * 64 + nb;
                *(float2*)(out + o0) =
                    make_float2(acc2[mt][nt][0] + bb.x, acc2[mt][nt][1] + bb.y);
                *(float2*)(out + o1) =
                    make_float2(acc2[mt][nt][2] + bb.x, acc2[mt][nt][3] + bb.y);
            }
        }
    }
}

// ---------------------------------------------------------------------------
extern "C" void kernel_launch(void* const* d_in, const int* in_sizes, int n_in,
                              void* d_out, int out_size) {
    const float* q_equi = (const float*)d_in[0];
    const float* q_inv  = (const float*)d_in[1];
    const float* k_equi = (const float*)d_in[2];
    const float* k_inv  = (const float*)d_in[3];
    const float* Wq     = (const float*)d_in[4];
    const float* bq     = (const float*)d_in[5];
    const float* Wk     = (const float*)d_in[6];
    const float* bk     = (const float*)d_in[7];
    const float* W1     = (const float*)d_in[8];
    const float* b1     = (const float*)d_in[9];
    const float* W2     = (const float*)d_in[10];
    const float* b2     = (const float*)d_in[11];
    float* out = (float*)d_out;

    static int smem_set = 0;
    if (!smem_set) {
        cudaFuncSetAttribute(pair_mma_kernel,
                             cudaFuncAttributeMaxDynamicSharedMemorySize,
                             SMEM_TOTAL);
        smem_set = 1;
    }

    prep_kernel<<<BB * (NQ + NK), 128>>>(q_inv, k_inv, Wq, bq, Wk, bk, W1, b1);
    pair_mma_kernel<<<N_BLOCKS, NTHR, SMEM_TOTAL>>>(
        q_equi, k_equi, W1, W2, b2, out);
}

// round 12
// speedup vs baseline: 3.4847x; 1.0014x over previous
#include <cuda_runtime.h>
#include <cuda_fp16.h>
#include <cstdint>

#define BB 2
#define NQ 512
#define NK 512
#define D_FF 128

#define QT2 (NQ / 16)
#define KT2 (NK / 16)
#define N_TILES2 (BB * QT2 * KT2)   /* 2048 double-tiles (16q x 16k = 256 pairs) */
#define N_BLOCKS 148
#define NTHR 512

// Per-row GEMM-1 halves (b1 folded into qc)
__device__ float g_qc[BB * NQ * D_FF];
__device__ float g_kc[BB * NK * D_FF];

// ---------------------------------------------------------------------------
// Prep kernel: blocks [0,1024) -> q rows, [1024,2048) -> k rows.
// ---------------------------------------------------------------------------
__global__ void prep_kernel(const float* __restrict__ q_inv,
                            const float* __restrict__ k_inv,
                            const float* __restrict__ Wq,
                            const float* __restrict__ bq,
                            const float* __restrict__ Wk,
                            const float* __restrict__ bk,
                            const float* __restrict__ W1,
                            const float* __restrict__ b1) {
    int bid = blockIdx.x;
    int t = threadIdx.x;
    __shared__ float msg[64];
    if (bid < BB * NQ) {
        int row = bid;
        if (t < 64) {
            const float* qi = q_inv + (size_t)row * 128;
            float a0 = bq[t], a1 = 0.f;
            #pragma unroll 4
            for (int i = 0; i < 128; i += 2) {
                a0 = fmaf(qi[i],     Wq[i * 64 + t],       a0);
                a1 = fmaf(qi[i + 1], Wq[(i + 1) * 64 + t], a1);
            }
            msg[t] = a0 + a1;
        }
        __syncthreads();
        float a0 = b1[t], a1 = 0.f;
        #pragma unroll 4
        for (int m = 0; m < 64; m += 2) {
            a0 = fmaf(msg[m],     W1[m * 128 + t],       a0);
            a1 = fmaf(msg[m + 1], W1[(m + 1) * 128 + t], a1);
        }
        g_qc[(size_t)row * 128 + t] = a0 + a1;
    } else {
        int row = bid - BB * NQ;
        if (t < 64) {
            const float* ki = k_inv + (size_t)row * 128;
            float a0 = bk[t], a1 = 0.f;
            #pragma unroll 4
            for (int i = 0; i < 128; i += 2) {
                a0 = fmaf(ki[i],     Wk[i * 64 + t],       a0);
                a1 = fmaf(ki[i + 1], Wk[(i + 1) * 64 + t], a1);
            }
            msg[t] = a0 + a1;
        }
        __syncthreads();
        float a0 = 0.f, a1 = 0.f;
        #pragma unroll 4
        for (int m = 0; m < 64; m += 2) {
            a0 = fmaf(msg[m],     W1[(64 + m) * 128 + t],     a0);
            a1 = fmaf(msg[m + 1], W1[(64 + m + 1) * 128 + t], a1);
        }
        g_kc[(size_t)row * 128 + t] = a0 + a1;
    }
}

// ---------------------------------------------------------------------------
// fp16 mma helpers
// ---------------------------------------------------------------------------
// Byte offset of logical column c (halves) within a row: columns grouped by 16,
// permuted so thread t's fragment {2t,2t+1,8+2t,8+2t+1} is contiguous (8 bytes).
__device__ __forceinline__ int colb(int c) {
    int r = c & 15;
    int pos = ((r & 6) << 1) + ((r >> 3) & 1) * 2 + (r & 1);
    return ((c >> 4) << 5) + pos * 2;
}
__device__ __forceinline__ uint32_t f2h2(float lo, float hi) {
    __half2 h = __floats2half2_rn(lo, hi);
    return *reinterpret_cast<uint32_t*>(&h);
}
__device__ __forceinline__ void mma16(float* d,
                                      uint32_t a0, uint32_t a1, uint32_t a2,
                                      uint32_t a3, uint32_t b0, uint32_t b1) {
    asm("mma.sync.aligned.m16n8k16.row.col.f32.f16.f16.f32 "
        "{%0,%1,%2,%3}, {%4,%5,%6,%7}, {%8,%9}, {%0,%1,%2,%3};"
        : "+f"(d[0]), "+f"(d[1]), "+f"(d[2]), "+f"(d[3])
        : "r"(a0), "r"(a1), "r"(a2), "r"(a3), "r"(b0), "r"(b1));
}

// ---------------------------------------------------------------------------
// SMEM layout (byte offsets). Row strides 160/288 bytes (==32 mod 128) make
// every fragment LDS.64 bank-conflict-free (8g+2t covers all 32 banks/phase).
// ---------------------------------------------------------------------------
#define SW1T 0                 /* 128 n-rows x 160 B (64 k halves)  */
#define SW2T 20480             /* 64  n-rows x 288 B (128 k halves) */
#define SA   38912             /* 256 m-rows x 160 B (64 halves)    */
#define SH   79872             /* 256 m-rows x 288 B (128 halves)   */
#define QCS  153600            /* 16 x 136 f32 */
#define KCS  162304            /* 16 x 136 f32 */
#define QES  171008            /* 16 x 97 f32  */
#define KES  177216            /* 16 x 97 f32  */
#define B2S  183424            /* 64 f32 */
#define SMEM_TOTAL 183680

__global__ __launch_bounds__(NTHR, 1)
void pair_mma_kernel(const float* __restrict__ q_equi,
                     const float* __restrict__ k_equi,
                     const float* __restrict__ W1,
                     const float* __restrict__ W2,
                     const float* __restrict__ b2,
                     float* __restrict__ out) {
    extern __shared__ char smc[];
    float* b2s = (float*)(smc + B2S);

    const int tid = threadIdx.x;

    // ---- one-time static staging: W1 pairwise rows + W2 as fp16, k-contig ----
    for (int i = tid; i < 128 * 64; i += NTHR) {     // sW1T[n][c] = W1[128+c][n]
        int n = i >> 6, c = i & 63;
        *(__half*)(smc + SW1T + n * 160 + colb(c)) =
            __float2half_rn(W1[(128 + c) * D_FF + n]);
    }
    for (int i = tid; i < 64 * 128; i += NTHR) {     // sW2T[n][k] = W2[k][n]
        int n = i >> 7, k = i & 127;
        *(__half*)(smc + SW2T + n * 288 + colb(k)) =
            __float2half_rn(W2[k * 64 + n]);
    }
    if (tid < 64) b2s[tid] = b2[tid];

    const int warp = tid >> 5, lane = tid & 31;
    const int wm = warp >> 1, wn = warp & 1;     // 8 m-strips(32) x 2 n-strips
    const int g = lane >> 2, t = lane & 3;
    const int m0 = wm * 32;

    const int fp = tid >> 1, fh = tid & 1;       // feature phase: 2 thr/pair
    const int fql = fp >> 4, fkl = fp & 15;

    for (int tile = blockIdx.x; tile < N_TILES2; tile += N_BLOCKS) {
        const int b  = tile / (QT2 * KT2);
        const int r  = tile % (QT2 * KT2);
        const int q0 = (r / KT2) * 16;
        const int k0 = (r % KT2) * 16;

        __syncthreads();   // prev iteration fully consumed dynamic buffers

        // ---- per-tile staging: qc/kc (f32) + equi tiles ----
        float* qcs = (float*)(smc + QCS);
        float* kcs = (float*)(smc + KCS);
        for (int i = tid; i < 16 * 128; i += NTHR)
            qcs[(i >> 7) * 136 + (i & 127)] =
                g_qc[(size_t)(b * NQ + q0 + (i >> 7)) * D_FF + (i & 127)];
        for (int i = tid; i < 16 * 128; i += NTHR)
            kcs[(i >> 7) * 136 + (i & 127)] =
                g_kc[(size_t)(b * NK + k0 + (i >> 7)) * D_FF + (i & 127)];
        float* qes = (float*)(smc + QES);
        float* kes = (float*)(smc + KES);
        for (int i = tid; i < 16 * 96; i += NTHR)
            qes[(i / 96) * 97 + (i % 96)] = q_equi[(size_t)(b * NQ + q0) * 96 + i];
        for (int i = tid; i < 16 * 96; i += NTHR)
            kes[(i / 96) * 97 + (i % 96)] = k_equi[(size_t)(b * NK + k0) * 96 + i];
        __syncthreads();

        // ---- features -> sA as fp16 (dot cols 0..31, dist cols 32..63) ----
        {
            const float* qr = qes + fql * 97;    // warp-uniform row
            const float* kr = kes + fkl * 97;
            char* ar = smc + SA + fp * 160;
            #pragma unroll
            for (int e = 16 * fh; e < 16 * fh + 16; e += 2) {
                float qa0 = qr[e], qb0 = qr[32 + e], qc0 = qr[64 + e];
                float ka0 = kr[e], kb0 = kr[32 + e], kc0 = kr[64 + e];
                float qa1 = qr[e + 1], qb1 = qr[33 + e], qc1 = qr[65 + e];
                float ka1 = kr[e + 1], kb1 = kr[33 + e], kc1 = kr[65 + e];
                float dot0 = qa0 * ka0 + qb0 * kb0 + qc0 * kc0;
                float dot1 = qa1 * ka1 + qb1 * kb1 + qc1 * kc1;
                float d0 = qa0 - ka0, d1 = qb0 - kb0, d2 = qc0 - kc0;
                float e0 = qa1 - ka1, e1 = qb1 - kb1, e2 = qc1 - kc1;
                float dist0 = sqrtf(d0 * d0 + d1 * d1 + d2 * d2);
                float dist1 = sqrtf(e0 * e0 + e1 * e1 + e2 * e2);
                *(uint32_t*)(ar + colb(e))      = f2h2(dot0, dot1);
                *(uint32_t*)(ar + colb(32 + e)) = f2h2(dist0, dist1);
            }
        }
        __syncthreads();

        // ---- GEMM-1: rows m0..m0+31, cols wn*64..+64, K=64 (4 k-slabs) ----
        float acc1[2][8][4];
        #pragma unroll
        for (int mt = 0; mt < 2; mt++)
            #pragma unroll
            for (int nt = 0; nt < 8; nt++)
                #pragma unroll
                for (int rr = 0; rr < 4; rr++) acc1[mt][nt][rr] = 0.f;

        #pragma unroll
        for (int kk = 0; kk < 4; kk++) {
            uint2 aLo[2], aHi[2];
            #pragma unroll
            for (int mt = 0; mt < 2; mt++) {
                const char* ap = smc + SA + (m0 + mt * 16 + g) * 160 + kk * 32 + t * 8;
                aLo[mt] = *(const uint2*)ap;
                aHi[mt] = *(const uint2*)(ap + 8 * 160);
            }
            #pragma unroll
            for (int nt = 0; nt < 8; nt++) {
                uint2 bf = *(const uint2*)(smc + SW1T +
                                           (wn * 64 + nt * 8 + g) * 160 + kk * 32 + t * 8);
                mma16(acc1[0][nt], aLo[0].x, aHi[0].x, aLo[0].y, aHi[0].y, bf.x, bf.y);
                mma16(acc1[1][nt], aLo[1].x, aHi[1].x, aLo[1].y, aHi[1].y, bf.x, bf.y);
            }
        }

        // ---- epilogue 1: +qc +kc, silu, fp16 -> sH ----
        #pragma unroll
        for (int mt = 0; mt < 2; mt++) {
            const float* qrow = qcs + (wm * 2 + mt) * 136;   // warp-uniform
            const float* kr0  = kcs + g * 136;
            const float* kr1  = kcs + (g + 8) * 136;
            char* h0p = smc + SH + (m0 + mt * 16 + g) * 288;
            char* h1p = h0p + 8 * 288;
            #pragma unroll
            for (int nt = 0; nt < 8; nt++) {
                int nb = wn * 64 + nt * 8 + 2 * t;
                float2 qv  = *(const float2*)(qrow + nb);
                float2 kv0 = *(const float2*)(kr0 + nb);
                float2 kv1 = *(const float2*)(kr1 + nb);
                float h0 = acc1[mt][nt][0] + qv.x + kv0.x;
                float h1 = acc1[mt][nt][1] + qv.y + kv0.y;
                float h2 = acc1[mt][nt][2] + qv.x + kv1.x;
                float h3 = acc1[mt][nt][3] + qv.y + kv1.y;
                h0 = __fdividef(h0, 1.f + __expf(-h0));
                h1 = __fdividef(h1, 1.f + __expf(-h1));
                h2 = __fdividef(h2, 1.f + __expf(-h2));
                h3 = __fdividef(h3, 1.f + __expf(-h3));
                int gb = ((wn * 4 + (nt >> 1)) << 5) + t * 8 + (nt & 1) * 4;
                *(uint32_t*)(h0p + gb) = f2h2(h0, h1);
                *(uint32_t*)(h1p + gb) = f2h2(h2, h3);
            }
        }
        __syncthreads();

        // ---- GEMM-2: rows m0..m0+31, cols wn*32..+32, K=128 (8 k-slabs) ----
        float acc2[2][4][4];
        #pragma unroll
        for (int mt = 0; mt < 2; mt++)
            #pragma unroll
            for (int nt = 0; nt < 4; nt++)
                #pragma unroll
                for (int rr = 0; rr < 4; rr++) acc2[mt][nt][rr] = 0.f;

        #pragma unroll
        for (int kk = 0; kk < 8; kk++) {
            uint2 aLo[2], aHi[2];
            #pragma unroll
            for (int mt = 0; mt < 2; mt++) {
                const char* ap = smc + SH + (m0 + mt * 16 + g) * 288 + kk * 32 + t * 8;
                aLo[mt] = *(const uint2*)ap;
                aHi[mt] = *(const uint2*)(ap + 8 * 288);
            }
            #pragma unroll
            for (int nt = 0; nt < 4; nt++) {
                uint2 bf = *(const uint2*)(smc + SW2T +
                                           (wn * 32 + nt * 8 + g) * 288 + kk * 32 + t * 8);
                mma16(acc2[0][nt], aLo[0].x, aHi[0].x, aLo[0].y, aHi[0].y, bf.x, bf.y);
                mma16(acc2[1][nt], aLo[1].x, aHi[1].x, aLo[1].y, aHi[1].y, bf.x, bf.y);
            }
        }

        // ---- epilogue 2: +b2, direct store (row p: jq=p>>4, jk=p&15) ----
        #pragma unroll
        for (int nt = 0; nt < 4; nt++) {
            int nb = wn * 32 + nt * 8 + 2 * t;
            float2 bb = *(const float2*)(b2s + nb);
            #pragma unroll
            for (int mt = 0; mt < 2; mt++) {
                int p0 = m0 + mt * 16 + g;
                int p1 = p0 + 8;
                size_t o0 = ((size_t)(b * NQ + q0 + (p0 >> 4)) * NK + (k0 + (p0 & 15))) * 64 + nb;
                size_t o1 = ((size_t)(b * NQ + q0 + (p1 >> 4)) * NK + (k0 + (p1 & 15))) * 64 + nb;
                *(float2*)(out + o0) =
                    make_float2(acc2[mt][nt][0] + bb.x, acc2[mt][nt][1] + bb.y);
                *(float2*)(out + o1) =
                    make_float2(acc2[mt][nt][2] + bb.x, acc2[mt][nt][3] + bb.y);
            }
        }
    }
}

// ---------------------------------------------------------------------------
extern "C" void kernel_launch(void* const* d_in, const int* in_sizes, int n_in,
                              void* d_out, int out_size) {
    const float* q_equi = (const float*)d_in[0];
    const float* q_inv  = (const float*)d_in[1];
    const float* k_equi = (const float*)d_in[2];
    const float* k_inv  = (const float*)d_in[3];
    const float* Wq     = (const float*)d_in[4];
    const float* bq     = (const float*)d_in[5];
    const float* Wk     = (const float*)d_in[6];
    const float* bk     = (const float*)d_in[7];
    const float* W1     = (const float*)d_in[8];
    const float* b1     = (const float*)d_in[9];
    const float* W2     = (const float*)d_in[10];
    const float* b2     = (const float*)d_in[11];
    float* out = (float*)d_out;

    static int smem_set = 0;
    if (!smem_set) {
        cudaFuncSetAttribute(pair_mma_kernel,
                             cudaFuncAttributeMaxDynamicSharedMemorySize,
                             SMEM_TOTAL);
        smem_set = 1;
    }

    prep_kernel<<<BB * (NQ + NK), 128>>>(q_inv, k_inv, Wq, bq, Wk, bk, W1, b1);
    pair_mma_kernel<<<N_BLOCKS, NTHR, SMEM_TOTAL>>>(
        q_equi, k_equi, W1, W2, b2, out);
}